// round 1
// baseline (speedup 1.0000x reference)
#include <cuda_runtime.h>
#include <cuda_bf16.h>

// Problem constants
#define D      512
#define NQ     16384   // 128*128
#define NL     1024    // 32*32
#define NHEAD  8
#define DM     64

// Scratch (device globals — no runtime allocation allowed)
__device__ float g_qT  [D * NQ];   // 32 MB
__device__ float g_KT  [D * NL];   //  2 MB
__device__ float g_VT  [D * NL];   //  2 MB
__device__ float g_msgT[D * NQ];   // 32 MB
__device__ float g_mT  [D * NQ];   // 32 MB

// ---------------------------------------------------------------------------
// SGEMM: C[M,N] = A[M,K] @ B[K,N], row-major, M%128==0, N%128==0, K%8==0.
// 128x128 tile, K-step 8, 256 threads, 8x8 register microtile.
// ---------------------------------------------------------------------------
__global__ __launch_bounds__(256)
void sgemm128(const float* __restrict__ A, const float* __restrict__ B,
              float* __restrict__ C, int N, int K) {
    __shared__ float As[8][128];
    __shared__ float Bs[8][128];

    const int tid = threadIdx.x;
    const int m0 = blockIdx.y * 128;
    const int n0 = blockIdx.x * 128;

    const int tx = tid % 16;    // n microtile
    const int ty = tid / 16;    // m microtile

    // A load: one float4 per thread per k-step. 128 rows x 8 cols.
    const int arow = tid >> 1;          // 0..127
    const int acol = (tid & 1) * 4;     // 0 or 4
    // B load: one float4 per thread. 8 rows x 128 cols.
    const int brow = tid >> 5;          // 0..7
    const int bcol = (tid & 31) * 4;    // 0..124

    float acc[8][8];
#pragma unroll
    for (int i = 0; i < 8; i++)
#pragma unroll
        for (int j = 0; j < 8; j++) acc[i][j] = 0.0f;

    for (int k0 = 0; k0 < K; k0 += 8) {
        float4 a = *(const float4*)(A + (size_t)(m0 + arow) * K + k0 + acol);
        As[acol + 0][arow] = a.x;
        As[acol + 1][arow] = a.y;
        As[acol + 2][arow] = a.z;
        As[acol + 3][arow] = a.w;
        float4 b = *(const float4*)(B + (size_t)(k0 + brow) * N + n0 + bcol);
        *(float4*)&Bs[brow][bcol] = b;
        __syncthreads();

#pragma unroll
        for (int kk = 0; kk < 8; kk++) {
            float ar[8], br[8];
#pragma unroll
            for (int i = 0; i < 8; i++) ar[i] = As[kk][ty * 8 + i];
#pragma unroll
            for (int j = 0; j < 8; j++) br[j] = Bs[kk][tx * 8 + j];
#pragma unroll
            for (int i = 0; i < 8; i++)
#pragma unroll
                for (int j = 0; j < 8; j++)
                    acc[i][j] = fmaf(ar[i], br[j], acc[i][j]);
        }
        __syncthreads();
    }

#pragma unroll
    for (int i = 0; i < 8; i++) {
        const int m = m0 + ty * 8 + i;
#pragma unroll
        for (int j = 0; j < 8; j += 4) {
            float4 v = make_float4(acc[i][j], acc[i][j + 1], acc[i][j + 2], acc[i][j + 3]);
            *(float4*)(C + (size_t)m * N + n0 + tx * 8 + j) = v;
        }
    }
}

// ---------------------------------------------------------------------------
// Windowed attention. One block per 4x4 guide tile (all 16 queries share the
// same 3x3 key window since y0 = Y//4). 128 threads = 16 queries x 8 heads.
// Dynamic smem: q[16][512] + msg[16][512] + K[9][512] + V[9][512] = 100 KB.
// ---------------------------------------------------------------------------
__global__ __launch_bounds__(128)
void attn_kernel(const float* __restrict__ qT, const float* __restrict__ KT,
                 const float* __restrict__ VT, float* __restrict__ msgT) {
    extern __shared__ float sm[];
    float* qs = sm;                 // [16][512]
    float* ms = qs + 16 * 512;      // [16][512]
    float* ks = ms + 16 * 512;      // [9][512]
    float* vs = ks + 9 * 512;       // [9][512]

    const int by = blockIdx.y;      // 0..31  (query Y tile == key center y)
    const int bx = blockIdx.x;      // 0..31
    const int tid = threadIdx.x;

    // Load q tile (coalesced-ish: 16 consecutive threads share c, 4x4B runs)
    for (int idx = tid; idx < 16 * 512; idx += 128) {
        const int c  = idx >> 4;
        const int qi = idx & 15;
        const int n  = (4 * by + (qi >> 2)) * 128 + 4 * bx + (qi & 3);
        qs[qi * 512 + c] = qT[(size_t)c * NQ + n];
    }

    // Load 9 K/V vectors (KT/VT are 2 MB each -> L2-resident)
    for (int idx = tid; idx < 9 * 512; idx += 128) {
        const int k = idx >> 9;
        const int c = idx & 511;
        const int dy = k / 3 - 1;
        const int dx = k % 3 - 1;
        const int yy = min(max(by + dy, 0), 31);
        const int xx = min(max(bx + dx, 0), 31);
        const int pos = yy * 32 + xx;
        ks[k * 512 + c] = KT[(size_t)c * NL + pos];
        vs[k * 512 + c] = VT[(size_t)c * NL + pos];
    }
    __syncthreads();

    // One (query, head) pair per thread
    const int qi = tid >> 3;
    const int h  = tid & 7;
    const float* qp = qs + qi * 512 + h * DM;

    float sc[9];
#pragma unroll
    for (int k = 0; k < 9; k++) {
        const float* kp = ks + k * 512 + h * DM;
        float s = 0.0f;
#pragma unroll
        for (int d = 0; d < DM; d++) s = fmaf(qp[d], kp[d], s);
        sc[k] = s * 0.125f;   // 1/sqrt(64)
    }

    float mx = sc[0];
#pragma unroll
    for (int k = 1; k < 9; k++) mx = fmaxf(mx, sc[k]);
    float sum = 0.0f;
#pragma unroll
    for (int k = 0; k < 9; k++) { sc[k] = __expf(sc[k] - mx); sum += sc[k]; }
    const float inv = 1.0f / sum;

    float* mp = ms + qi * 512 + h * DM;
#pragma unroll 4
    for (int d = 0; d < DM; d++) {
        float acc = 0.0f;
#pragma unroll
        for (int k = 0; k < 9; k++) acc = fmaf(sc[k], vs[k * 512 + h * DM + d], acc);
        mp[d] = acc * inv;
    }
    __syncthreads();

    // Write msgT (channel-major)
    for (int idx = tid; idx < 16 * 512; idx += 128) {
        const int c  = idx >> 4;
        const int qi2 = idx & 15;
        const int n  = (4 * by + (qi2 >> 2)) * 128 + 4 * bx + (qi2 & 3);
        msgT[(size_t)c * NQ + n] = ms[qi2 * 512 + c];
    }
}

// ---------------------------------------------------------------------------
// Channel LayerNorm on [c, n] layout; output is already [d, H, W].
// One thread per column n; row reads are coalesced across the warp.
// ---------------------------------------------------------------------------
__global__ __launch_bounds__(256)
void ln_kernel(const float* __restrict__ mT, const float* __restrict__ gamma,
               const float* __restrict__ beta, float* __restrict__ out) {
    const int n = blockIdx.x * blockDim.x + threadIdx.x;
    float s = 0.0f, s2 = 0.0f;
    for (int c = 0; c < D; c++) {
        const float x = mT[(size_t)c * NQ + n];
        s += x; s2 += x * x;
    }
    const float mu = s * (1.0f / D);
    const float var = s2 * (1.0f / D) - mu * mu;
    const float r = rsqrtf(var + 1e-5f);
    for (int c = 0; c < D; c++) {
        const float x = mT[(size_t)c * NQ + n];
        out[(size_t)c * NQ + n] = (x - mu) * r * gamma[c] + beta[c];
    }
}

// ---------------------------------------------------------------------------
extern "C" void kernel_launch(void* const* d_in, const int* in_sizes, int n_in,
                              void* d_out, int out_size) {
    const float* low   = (const float*)d_in[0];   // [1,512,32,32]
    const float* guide = (const float*)d_in[1];   // [1,512,128,128]
    const float* Wq    = (const float*)d_in[2];   // [512,512]
    const float* Wk    = (const float*)d_in[3];
    const float* Wv    = (const float*)d_in[4];
    const float* Wm    = (const float*)d_in[5];
    const float* gamma = (const float*)d_in[6];
    const float* beta  = (const float*)d_in[7];
    float* out = (float*)d_out;

    float *qT, *KT, *VT, *msgT, *mT;
    cudaGetSymbolAddress((void**)&qT,   g_qT);
    cudaGetSymbolAddress((void**)&KT,   g_KT);
    cudaGetSymbolAddress((void**)&VT,   g_VT);
    cudaGetSymbolAddress((void**)&msgT, g_msgT);
    cudaGetSymbolAddress((void**)&mT,   g_mT);

    // Projections (channel-major GEMMs)
    sgemm128<<<dim3(NQ / 128, D / 128), 256>>>(Wq, guide, qT, NQ, D);
    sgemm128<<<dim3(NL / 128, D / 128), 256>>>(Wk, low,   KT, NL, D);
    sgemm128<<<dim3(NL / 128, D / 128), 256>>>(Wv, low,   VT, NL, D);

    // Windowed attention
    cudaFuncSetAttribute(attn_kernel, cudaFuncAttributeMaxDynamicSharedMemorySize, 102400);
    attn_kernel<<<dim3(32, 32), 128, 102400>>>(qT, KT, VT, msgT);

    // Output projection + LayerNorm (writes final [d,H,W] layout)
    sgemm128<<<dim3(NQ / 128, D / 128), 256>>>(Wm, msgT, mT, NQ, D);
    ln_kernel<<<NQ / 256, 256>>>(mT, gamma, beta, out);
}

// round 3
// speedup vs baseline: 3.3132x; 3.3132x over previous
#include <cuda_runtime.h>
#include <cuda_bf16.h>
#include <cstdint>

#define D_    512
#define NQ_   16384
#define NL_   1024

// ============================ scratch ============================
__device__ float g_q  [NQ_ * D_];
__device__ float g_K  [NL_ * D_];
__device__ float g_V  [NL_ * D_];
__device__ float g_msg[NQ_ * D_];
__device__ float g_mT [NQ_ * D_];
__device__ float2 g_stats[NQ_];

// ============================ helpers ============================
__device__ __forceinline__ uint32_t smem_u32(const void* p) {
    uint32_t a;
    asm("{ .reg .u64 t; cvta.to.shared.u64 t, %1; cvt.u32.u64 %0, t; }" : "=r"(a) : "l"(p));
    return a;
}

__device__ __forceinline__ void ldsm_x4(uint32_t* r, uint32_t addr) {
    asm volatile("ldmatrix.sync.aligned.m8n8.x4.shared.b16 {%0,%1,%2,%3}, [%4];"
                 : "=r"(r[0]), "=r"(r[1]), "=r"(r[2]), "=r"(r[3]) : "r"(addr));
}
__device__ __forceinline__ void ldsm_x4_t(uint32_t* r, uint32_t addr) {
    asm volatile("ldmatrix.sync.aligned.m8n8.x4.trans.shared.b16 {%0,%1,%2,%3}, [%4];"
                 : "=r"(r[0]), "=r"(r[1]), "=r"(r[2]), "=r"(r[3]) : "r"(addr));
}
__device__ __forceinline__ void mma_bf16(float* d, const uint32_t* a, uint32_t b0, uint32_t b1) {
    asm volatile(
        "mma.sync.aligned.m16n8k16.row.col.f32.bf16.bf16.f32 "
        "{%0,%1,%2,%3}, {%4,%5,%6,%7}, {%8,%9}, {%0,%1,%2,%3};"
        : "+f"(d[0]), "+f"(d[1]), "+f"(d[2]), "+f"(d[3])
        : "r"(a[0]), "r"(a[1]), "r"(a[2]), "r"(a[3]), "r"(b0), "r"(b1));
}

__device__ __forceinline__ void split2(float2 v, uint32_t& h, uint32_t& l) {
    __nv_bfloat16 hx = __float2bfloat16(v.x);
    __nv_bfloat16 hy = __float2bfloat16(v.y);
    __nv_bfloat162 h2; h2.x = hx; h2.y = hy;
    __nv_bfloat162 l2;
    l2.x = __float2bfloat16(v.x - __bfloat162float(hx));
    l2.y = __float2bfloat16(v.y - __bfloat162float(hy));
    h = *(uint32_t*)&h2; l = *(uint32_t*)&l2;
}

// ============================ mma.sync GEMM ============================
// C[m, n] = sum_k A[m,k] * B[n,k], n over 512 weights rows, k = 512.
// TRANS=1: A stored channel-major [512 k][M] (activations as given).
// TRANS=0: A stored token-major  [M][512 k].
// fp32 inputs are split to bf16 hi/lo on the fly; 3 MMAs (hh + hl + lh).
// CTA tile 128m x 128n, 8 warps (2m x 4n), warp tile 64m x 32n.
template<int TRANS>
__global__ __launch_bounds__(256, 1)
void gemm_mma(const float* __restrict__ A, const float* __restrict__ Bw,
              float* __restrict__ C, int M) {
    extern __shared__ char sm[];
    constexpr int ASZ = TRANS ? 64 * 272 : 128 * 144;   // bytes (hi part)
    char* sAh = sm;
    char* sAl = sm + ASZ;
    char* sBh = sm + 2 * ASZ;
    char* sBl = sBh + 128 * 144;

    const int tid  = threadIdx.x;
    const int lane = tid & 31;
    const int warp = tid >> 5;
    const int wm = (warp & 1) * 64;
    const int wn = (warp >> 1) * 32;
    const int m0 = blockIdx.x * 128;
    const int n0 = blockIdx.y * 128;

    const uint32_t a_base = smem_u32(sAh);
    const uint32_t b_base = smem_u32(sBh);

    uint32_t aoff0;
    if (TRANS) {
        const int krow = ((lane >> 4) & 1) * 8 + (lane & 7);
        const int mcol = ((lane >> 3) & 1) * 8;
        aoff0 = (uint32_t)(krow * 272 + (wm + mcol) * 2);
    } else {
        const int arow = lane & 15;
        const int koff = ((lane >> 4) & 1) * 8;
        aoff0 = (uint32_t)((wm + arow) * 144 + koff * 2);
    }
    const int nrow  = (lane & 7) + ((lane >> 4) & 1) * 8;
    const int koffb = ((lane >> 3) & 1) * 8;
    const uint32_t boff0 = (uint32_t)((wn + nrow) * 144 + koffb * 2);

    float acc[4][4][4];
#pragma unroll
    for (int i = 0; i < 4; i++)
#pragma unroll
        for (int j = 0; j < 4; j++)
#pragma unroll
            for (int r = 0; r < 4; r++) acc[i][j][r] = 0.f;

    float2 stA[16], stB[16];

#define LOAD_STAGE(CH) do {                                                     \
    const int k0 = (CH) * 64;                                                   \
    _Pragma("unroll")                                                           \
    for (int it = 0; it < 16; it++) {                                           \
        const int idx = tid + it * 256;                                         \
        if (TRANS) {                                                            \
            const int k = idx >> 6, mp = idx & 63;                              \
            stA[it] = *(const float2*)(A + (size_t)(k0 + k) * M + m0 + 2 * mp); \
        } else {                                                                \
            const int m = idx >> 5, kp = idx & 31;                              \
            stA[it] = *(const float2*)(A + (size_t)(m0 + m) * 512 + k0 + 2 * kp);\
        }                                                                       \
        const int nn = idx >> 5, kp2 = idx & 31;                                \
        stB[it] = *(const float2*)(Bw + (size_t)(n0 + nn) * 512 + k0 + 2 * kp2);\
    }                                                                           \
} while (0)

#define STORE_STAGE() do {                                                      \
    _Pragma("unroll")                                                           \
    for (int it = 0; it < 16; it++) {                                           \
        const int idx = tid + it * 256;                                         \
        uint32_t h, l;                                                          \
        split2(stA[it], h, l);                                                  \
        uint32_t off;                                                           \
        if (TRANS) { const int k = idx >> 6, mp = idx & 63; off = k * 272 + mp * 4; } \
        else       { const int m = idx >> 5, kp = idx & 31; off = m * 144 + kp * 4; } \
        *(uint32_t*)(sAh + off) = h;  *(uint32_t*)(sAl + off) = l;              \
        split2(stB[it], h, l);                                                  \
        const int nn = idx >> 5, kp2 = idx & 31;                                \
        const uint32_t offb = nn * 144 + kp2 * 4;                               \
        *(uint32_t*)(sBh + offb) = h; *(uint32_t*)(sBl + offb) = l;             \
    }                                                                           \
} while (0)

    LOAD_STAGE(0);
    STORE_STAGE();
    __syncthreads();

    for (int ch = 0; ch < 8; ch++) {
        if (ch < 7) LOAD_STAGE(ch + 1);

#pragma unroll
        for (int ks = 0; ks < 4; ks++) {
            uint32_t ah[4][4], al[4][4], bh[2][4], bl[2][4];
#pragma unroll
            for (int mi = 0; mi < 4; mi++) {
                uint32_t ao;
                if (TRANS) ao = aoff0 + ks * 16 * 272 + mi * 32;
                else       ao = aoff0 + mi * 16 * 144 + ks * 32;
                if (TRANS) { ldsm_x4_t(ah[mi], a_base + ao); ldsm_x4_t(al[mi], a_base + ASZ + ao); }
                else       { ldsm_x4 (ah[mi], a_base + ao); ldsm_x4 (al[mi], a_base + ASZ + ao); }
            }
#pragma unroll
            for (int nt = 0; nt < 2; nt++) {
                const uint32_t bo = boff0 + nt * 16 * 144 + ks * 32;
                ldsm_x4(bh[nt], b_base + bo);
                ldsm_x4(bl[nt], b_base + 18432 + bo);
            }
#pragma unroll
            for (int mi = 0; mi < 4; mi++) {
#pragma unroll
                for (int j = 0; j < 4; j++) {
                    const uint32_t bh0 = bh[j >> 1][(j & 1) * 2];
                    const uint32_t bh1 = bh[j >> 1][(j & 1) * 2 + 1];
                    const uint32_t bl0 = bl[j >> 1][(j & 1) * 2];
                    const uint32_t bl1 = bl[j >> 1][(j & 1) * 2 + 1];
                    mma_bf16(acc[mi][j], ah[mi], bh0, bh1);
                    mma_bf16(acc[mi][j], ah[mi], bl0, bl1);
                    mma_bf16(acc[mi][j], al[mi], bh0, bh1);
                }
            }
        }
        __syncthreads();
        if (ch < 7) { STORE_STAGE(); __syncthreads(); }
    }

    const int g = lane >> 2, t = lane & 3;
#pragma unroll
    for (int mi = 0; mi < 4; mi++) {
#pragma unroll
        for (int j = 0; j < 4; j++) {
            const int row = m0 + wm + mi * 16 + g;
            const int col = n0 + wn + j * 8 + 2 * t;
            *(float2*)(C + (size_t)row * 512 + col)       = make_float2(acc[mi][j][0], acc[mi][j][1]);
            *(float2*)(C + (size_t)(row + 8) * 512 + col) = make_float2(acc[mi][j][2], acc[mi][j][3]);
        }
    }
#undef LOAD_STAGE
#undef STORE_STAGE
}

// ============================ attention ============================
// q: [NQ,512] fp32; K,V: [NL,512] fp32; msg: [NQ,512] fp32.
// One block per 4x4 guide tile (shared 3x3 key window). 128 thr = 16 q x 8 h.
__global__ __launch_bounds__(128)
void attn(const float* __restrict__ q, const float* __restrict__ Kb,
          const float* __restrict__ Vb, float* __restrict__ msg) {
    extern __shared__ float4 s4[];
    float4* qs = s4;                 // 16 x 129
    float4* ks = qs + 16 * 129;      // 9 x 129
    float4* vs = ks + 9 * 129;       // 9 x 129

    const int by = blockIdx.y, bx = blockIdx.x;
    const int tid = threadIdx.x;

    for (int t = tid; t < 2048; t += 128) {
        const int qi = t >> 7, i = t & 127;
        const int n = (4 * by + (qi >> 2)) * 128 + 4 * bx + (qi & 3);
        qs[qi * 129 + i] = ((const float4*)(q + (size_t)n * D_))[i];
    }
    for (int t = tid; t < 1152; t += 128) {
        const int k = t >> 7, i = t & 127;
        const int yy = min(max(by + k / 3 - 1, 0), 31);
        const int xx = min(max(bx + k % 3 - 1, 0), 31);
        const int pos = yy * 32 + xx;
        ks[k * 129 + i] = ((const float4*)(Kb + (size_t)pos * D_))[i];
        vs[k * 129 + i] = ((const float4*)(Vb + (size_t)pos * D_))[i];
    }
    __syncthreads();

    const int qi = tid & 15;
    const int h = tid >> 4;
    const float4* qp = qs + qi * 129 + h * 16;

    float sc[9];
#pragma unroll
    for (int k = 0; k < 9; k++) {
        const float4* kp = ks + k * 129 + h * 16;
        float s = 0.f;
#pragma unroll
        for (int d4 = 0; d4 < 16; d4++) {
            const float4 a = qp[d4], b = kp[d4];
            s = fmaf(a.x, b.x, s); s = fmaf(a.y, b.y, s);
            s = fmaf(a.z, b.z, s); s = fmaf(a.w, b.w, s);
        }
        sc[k] = s * 0.125f;
    }
    float mx = sc[0];
#pragma unroll
    for (int k = 1; k < 9; k++) mx = fmaxf(mx, sc[k]);
    float sum = 0.f;
#pragma unroll
    for (int k = 0; k < 9; k++) { sc[k] = __expf(sc[k] - mx); sum += sc[k]; }
    const float inv = 1.f / sum;
#pragma unroll
    for (int k = 0; k < 9; k++) sc[k] *= inv;

    const int n = (4 * by + (qi >> 2)) * 128 + 4 * bx + (qi & 3);
    float4* mp = (float4*)(msg + (size_t)n * D_ + h * 64);
#pragma unroll 4
    for (int d4 = 0; d4 < 16; d4++) {
        float ax = 0.f, ay = 0.f, az = 0.f, aw = 0.f;
#pragma unroll
        for (int k = 0; k < 9; k++) {
            const float4 v = vs[k * 129 + h * 16 + d4];
            ax = fmaf(sc[k], v.x, ax); ay = fmaf(sc[k], v.y, ay);
            az = fmaf(sc[k], v.z, az); aw = fmaf(sc[k], v.w, aw);
        }
        mp[d4] = make_float4(ax, ay, az, aw);
    }
}

// ============================ LayerNorm ============================
__global__ __launch_bounds__(256)
void ln_stats(const float* __restrict__ m, float2* __restrict__ stats) {
    const int warp = threadIdx.x >> 5, lane = threadIdx.x & 31;
    const int n = blockIdx.x * 8 + warp;
    const float4* row = (const float4*)(m + (size_t)n * D_);
    float s = 0.f, s2 = 0.f;
#pragma unroll
    for (int i = 0; i < 4; i++) {
        const float4 v = row[lane + 32 * i];
        s  += v.x + v.y + v.z + v.w;
        s2 += v.x * v.x + v.y * v.y + v.z * v.z + v.w * v.w;
    }
#pragma unroll
    for (int o = 16; o; o >>= 1) {
        s  += __shfl_xor_sync(0xFFFFFFFFu, s, o);
        s2 += __shfl_xor_sync(0xFFFFFFFFu, s2, o);
    }
    if (lane == 0) {
        const float mu = s * (1.f / 512.f);
        const float rstd = rsqrtf(s2 * (1.f / 512.f) - mu * mu + 1e-5f);
        stats[n] = make_float2(mu, rstd);
    }
}

// apply LN + transpose token-major [n][c] -> channel-major out[c][n]
__global__ __launch_bounds__(256)
void ln_apply(const float* __restrict__ m, const float2* __restrict__ stats,
              const float* __restrict__ gamma, const float* __restrict__ beta,
              float* __restrict__ out) {
    __shared__ float t[32][33];
    const int n0 = blockIdx.x * 32, c0 = blockIdx.y * 32;
    const int tx = threadIdx.x, ty = threadIdx.y;
#pragma unroll
    for (int j = 0; j < 32; j += 8)
        t[ty + j][tx] = m[(size_t)(n0 + ty + j) * 512 + c0 + tx];
    __syncthreads();
#pragma unroll
    for (int j = 0; j < 32; j += 8) {
        const int c = c0 + ty + j;
        const int n = n0 + tx;
        const float2 st = stats[n];
        out[(size_t)c * NQ_ + n] = (t[tx][ty + j] - st.x) * st.y * gamma[c] + beta[c];
    }
}

// ============================ launch ============================
extern "C" void kernel_launch(void* const* d_in, const int* in_sizes, int n_in,
                              void* d_out, int out_size) {
    const float* low   = (const float*)d_in[0];   // [1,512,32,32]
    const float* guide = (const float*)d_in[1];   // [1,512,128,128]
    const float* Wq    = (const float*)d_in[2];
    const float* Wk    = (const float*)d_in[3];
    const float* Wv    = (const float*)d_in[4];
    const float* Wm    = (const float*)d_in[5];
    const float* gamma = (const float*)d_in[6];
    const float* beta  = (const float*)d_in[7];
    float* out = (float*)d_out;

    float *qb, *Kb, *Vb, *msg, *mT;
    float2* stats;
    cudaGetSymbolAddress((void**)&qb,    g_q);
    cudaGetSymbolAddress((void**)&Kb,    g_K);
    cudaGetSymbolAddress((void**)&Vb,    g_V);
    cudaGetSymbolAddress((void**)&msg,   g_msg);
    cudaGetSymbolAddress((void**)&mT,    g_mT);
    cudaGetSymbolAddress((void**)&stats, g_stats);

    const int SM_G1 = 2 * (64 * 272) + 2 * (128 * 144);   // 71680
    const int SM_G0 = 4 * (128 * 144);                    // 73728
    const int SM_ATTN = 34 * 129 * 16;                    // 70176
    cudaFuncSetAttribute(gemm_mma<1>, cudaFuncAttributeMaxDynamicSharedMemorySize, SM_G1);
    cudaFuncSetAttribute(gemm_mma<0>, cudaFuncAttributeMaxDynamicSharedMemorySize, SM_G0);
    cudaFuncSetAttribute(attn, cudaFuncAttributeMaxDynamicSharedMemorySize, SM_ATTN);

    // Projections (fused fp32->bf16 split, channel-major A via ldmatrix.trans)
    gemm_mma<1><<<dim3(NQ_ / 128, 4), 256, SM_G1>>>(guide, Wq, qb, NQ_);
    gemm_mma<1><<<dim3(NL_ / 128, 4), 256, SM_G1>>>(low,   Wk, Kb, NL_);
    gemm_mma<1><<<dim3(NL_ / 128, 4), 256, SM_G1>>>(low,   Wv, Vb, NL_);

    // Windowed attention
    attn<<<dim3(32, 32), 128, SM_ATTN>>>(qb, Kb, Vb, msg);

    // Output projection (token-major A) + LayerNorm + transpose
    gemm_mma<0><<<dim3(NQ_ / 128, 4), 256, SM_G0>>>(msg, Wm, mT, NQ_);
    ln_stats<<<NQ_ / 8, 256>>>(mT, stats);
    ln_apply<<<dim3(NQ_ / 32, D_ / 32), dim3(32, 8)>>>(mT, stats, gamma, beta, out);
}